// round 2
// baseline (speedup 1.0000x reference)
#include <cuda_runtime.h>
#include <cstdint>
#include <cstring>

// AFM fused kernel, fp32 with packed fma.rn.f32x2 (sm_103a FFMA2).
// One CTA per batch element. B=1024, F=33 (P=528 pairs), D=A=128.

#define F_   33
#define D_   128
#define A_   128
#define P_   528
#define THREADS_ 256
#define MTILE 64
#define NTILES 9

#define FMA_F32X2(d, a, b, c) \
    asm("fma.rn.f32x2 %0, %1, %2, %3;" : "=l"(d) : "l"(a), "l"(b), "l"(c))

struct Smem {
    float xs[F_][132];        // x[b], row stride 132 (16B-aligned)
    float Ws[A_][132];        // W native layout: Ws[a][k], k contiguous
    float Is[MTILE][132];     // inner tile, m-major: Is[m][k], k contiguous
    float scores[P_];
    float red[16];
    unsigned short pairs[P_];
};

static __device__ __forceinline__ float2 u64_as_f2(uint64_t v) {
    float2 f; memcpy(&f, &v, 8); return f;
}

__global__ void __launch_bounds__(THREADS_, 1)
afm_kernel(const float* __restrict__ gnn,
           const float* __restrict__ x,
           const float* __restrict__ W,
           const float* __restrict__ bias,
           float* __restrict__ out)
{
    extern __shared__ unsigned char smem_raw[];
    Smem* s = reinterpret_cast<Smem*>(smem_raw);

    const int b    = blockIdx.x;
    const int tid  = threadIdx.x;
    const int lane = tid & 31;
    const int wid  = tid >> 5;
    const int tm   = tid & 15;     // 16 m-quads -> 64 m rows
    const int tn   = tid >> 4;     // 16 a-octets -> 128 a cols

    // ---- pair table (row-major triu, k=1) ----
    for (int p = tid; p < P_; p += THREADS_) {
        int i = 0, base = 0;
        while (base + (F_ - 1 - i) <= p) { base += F_ - 1 - i; ++i; }
        int j = i + 1 + (p - base);
        s->pairs[p] = (unsigned short)((i << 8) | j);
    }
    for (int p = tid; p < P_; p += THREADS_) s->scores[p] = 0.f;

    // ---- load x[b] (float4, coalesced) ----
    const float4* xb = reinterpret_cast<const float4*>(x + (size_t)b * F_ * D_);
    for (int e = tid; e < F_ * D_ / 4; e += THREADS_) {
        int f = e >> 5, q = e & 31;
        *reinterpret_cast<float4*>(&s->xs[f][q * 4]) = xb[e];
    }
    // ---- load W native layout: Ws[a][k] ----
    const float4* Wv = reinterpret_cast<const float4*>(W);
    for (int e = tid; e < A_ * D_ / 4; e += THREADS_) {
        int a = e >> 5, q = e & 31;
        *reinterpret_cast<float4*>(&s->Ws[a][q * 4]) = Wv[e];
    }
    __syncthreads();

    const int a0 = tn * 8;
    float greg[8], breg[8];
#pragma unroll
    for (int n = 0; n < 8; ++n) {
        greg[n] = gnn[(size_t)b * A_ + a0 + n];
        breg[n] = bias[a0 + n];
    }

    // ==== main loop over M-tiles of pairs ====
    for (int t = 0; t < NTILES; ++t) {
        const int m0 = t * MTILE;
        __syncthreads();   // previous tile's Is reads complete

        // fill Is[mloc][k] = xs[i][k]*xs[j][k]; warp lanes cover k-quads of
        // one row -> conflict-free reads and stores.
        for (int e = tid; e < MTILE * 32; e += THREADS_) {
            int mloc = e >> 5, q = e & 31;
            int m = m0 + mloc;
            float4 v = make_float4(0.f, 0.f, 0.f, 0.f);
            if (m < P_) {
                unsigned short pr = s->pairs[m];
                float4 xi = *reinterpret_cast<const float4*>(&s->xs[pr >> 8][q * 4]);
                float4 xj = *reinterpret_cast<const float4*>(&s->xs[pr & 255][q * 4]);
                v = make_float4(xi.x * xj.x, xi.y * xj.y, xi.z * xj.z, xi.w * xj.w);
            }
            *reinterpret_cast<float4*>(&s->Is[mloc][q * 4]) = v;
        }
        __syncthreads();

        // register-tiled GEMM with k-packed f32x2:
        // acc[mi][ni] holds {sum over even k, sum over odd k}
        uint64_t acc[4][8];
#pragma unroll
        for (int mi = 0; mi < 4; ++mi)
#pragma unroll
            for (int ni = 0; ni < 8; ++ni) acc[mi][ni] = 0ull;

        const int mrow = tm * 4;
#pragma unroll 2
        for (int kk = 0; kk < D_; kk += 4) {
            uint64_t im2[4][2];
#pragma unroll
            for (int mi = 0; mi < 4; ++mi) {
                ulonglong2 v = *reinterpret_cast<const ulonglong2*>(&s->Is[mrow + mi][kk]);
                im2[mi][0] = v.x; im2[mi][1] = v.y;
            }
#pragma unroll
            for (int ni = 0; ni < 8; ++ni) {
                ulonglong2 w = *reinterpret_cast<const ulonglong2*>(&s->Ws[a0 + ni][kk]);
#pragma unroll
                for (int mi = 0; mi < 4; ++mi) {
                    FMA_F32X2(acc[mi][ni], im2[mi][0], w.x, acc[mi][ni]);
                    FMA_F32X2(acc[mi][ni], im2[mi][1], w.y, acc[mi][ni]);
                }
            }
        }

        // epilogue: fold k-halves, bias + relu + dot with gnn -> scores
#pragma unroll
        for (int mi = 0; mi < 4; ++mi) {
            int m = m0 + tm * 4 + mi;
            float sc = 0.f;
            if (m < P_) {
#pragma unroll
                for (int n = 0; n < 8; ++n) {
                    float2 pr = u64_as_f2(acc[mi][n]);
                    float z = fmaxf(pr.x + pr.y + breg[n], 0.f);
                    sc = fmaf(greg[n], z, sc);
                }
            }
            sc += __shfl_xor_sync(0xffffffffu, sc, 16);   // fold the 2 tn's in this warp
            if (lane < 16 && m < P_) atomicAdd(&s->scores[m], sc);
        }
    }
    __syncthreads();

    // ==== softmax over scores[528] ====
    float lmax = -1e30f;
    for (int p = tid; p < P_; p += THREADS_) lmax = fmaxf(lmax, s->scores[p]);
#pragma unroll
    for (int o = 16; o; o >>= 1) lmax = fmaxf(lmax, __shfl_xor_sync(0xffffffffu, lmax, o));
    if (lane == 0) s->red[wid] = lmax;
    __syncthreads();
    if (tid < 32) {
        float v = (tid < 8) ? s->red[tid] : -1e30f;
#pragma unroll
        for (int o = 4; o; o >>= 1) v = fmaxf(v, __shfl_xor_sync(0xffffffffu, v, o));
        if (tid == 0) s->red[8] = v;
    }
    __syncthreads();
    const float mx = s->red[8];

    float lsum = 0.f;
    for (int p = tid; p < P_; p += THREADS_) {
        float e = __expf(s->scores[p] - mx);
        s->scores[p] = e;
        lsum += e;
    }
#pragma unroll
    for (int o = 16; o; o >>= 1) lsum += __shfl_xor_sync(0xffffffffu, lsum, o);
    if (lane == 0) s->red[wid] = lsum;
    __syncthreads();
    if (tid < 32) {
        float v = (tid < 8) ? s->red[tid] : 0.f;
#pragma unroll
        for (int o = 4; o; o >>= 1) v += __shfl_xor_sync(0xffffffffu, v, o);
        if (tid == 0) s->red[9] = v;
    }
    __syncthreads();
    const float scale = 100.f / s->red[9];

    // ==== attn_output[d] = scale * sum_p exp_p * xs[i][d]*xs[j][d] ====
    const int d    = tid & 127;
    const int half = tid >> 7;
    float accd = 0.f;
    const int pstart = half * (P_ / 2);
    for (int p = pstart; p < pstart + P_ / 2; ++p) {
        unsigned short pr = s->pairs[p];
        accd = fmaf(s->scores[p], s->xs[pr >> 8][d] * s->xs[pr & 255][d], accd);
    }
    float* part = reinterpret_cast<float*>(s->Is);   // reuse Is as scratch [2][128]
    part[half * 128 + d] = accd;
    __syncthreads();

    float* outb = out + (size_t)b * (A_ + D_);
    if (tid < 128) {
        outb[tid]       = gnn[(size_t)b * A_ + tid];
        outb[128 + tid] = (part[tid] + part[128 + tid]) * scale;
    }
}

extern "C" void kernel_launch(void* const* d_in, const int* in_sizes, int n_in,
                              void* d_out, int out_size)
{
    const float* gnn  = (const float*)d_in[0];   // [B, 128]
    const float* x    = (const float*)d_in[1];   // [B, 33, 128]
    const float* W    = (const float*)d_in[2];   // [128, 128]
    const float* bias = (const float*)d_in[3];   // [128]
    float* out        = (float*)d_out;           // [B, 256]

    const int B = in_sizes[0] / A_;

    cudaFuncSetAttribute(afm_kernel, cudaFuncAttributeMaxDynamicSharedMemorySize,
                         (int)sizeof(Smem));
    afm_kernel<<<B, THREADS_, sizeof(Smem)>>>(gnn, x, W, bias, out);
}

// round 3
// speedup vs baseline: 1.5336x; 1.5336x over previous
#include <cuda_runtime.h>
#include <cstdint>
#include <cstring>

// AFM fused kernel. R1 conflict-free k-major smem layout + n-packed fma.rn.f32x2.
// One CTA per batch element. B=1024, F=33 (P=528 pairs), D=A=128.

#define F_   33
#define D_   128
#define A_   128
#define P_   528
#define THREADS_ 256
#define MTILE 64
#define NTILES 9

#define FMA_F32X2(d, a, b, c) \
    asm("fma.rn.f32x2 %0, %1, %2, %3;" : "=l"(d) : "l"(a), "l"(b), "l"(c))

#define PACK_DUP(d, f) \
    asm("mov.b64 %0, {%1, %1};" : "=l"(d) : "f"(f))

struct Smem {
    float xs[F_][132];       // x[b]
    float Ws[D_][132];       // W transposed: Ws[k][a], a contiguous
    float Is[D_][68];        // inner tile, k-major: Is[k][m], m contiguous
    float scores[P_];
    float red[16];
    unsigned short pairs[P_];
};

static __device__ __forceinline__ float2 u64_as_f2(uint64_t v) {
    float2 f; memcpy(&f, &v, 8); return f;
}

__global__ void __launch_bounds__(THREADS_, 1)
afm_kernel(const float* __restrict__ gnn,
           const float* __restrict__ x,
           const float* __restrict__ W,
           const float* __restrict__ bias,
           float* __restrict__ out)
{
    extern __shared__ unsigned char smem_raw[];
    Smem* s = reinterpret_cast<Smem*>(smem_raw);

    const int b    = blockIdx.x;
    const int tid  = threadIdx.x;
    const int lane = tid & 31;
    const int wid  = tid >> 5;
    const int tm   = tid & 15;     // 16 m-quads -> 64 m rows
    const int tn   = tid >> 4;     // 16 a-octets -> 128 a cols

    // ---- pair table (row-major triu, k=1) ----
    for (int p = tid; p < P_; p += THREADS_) {
        int i = 0, base = 0;
        while (base + (F_ - 1 - i) <= p) { base += F_ - 1 - i; ++i; }
        int j = i + 1 + (p - base);
        s->pairs[p] = (unsigned short)((i << 8) | j);
    }
    for (int p = tid; p < P_; p += THREADS_) s->scores[p] = 0.f;

    // ---- load x[b] (float4, coalesced) ----
    const float4* xb = reinterpret_cast<const float4*>(x + (size_t)b * F_ * D_);
    for (int e = tid; e < F_ * D_ / 4; e += THREADS_) {
        int f = e >> 5, q = e & 31;
        *reinterpret_cast<float4*>(&s->xs[f][q * 4]) = xb[e];
    }
    // ---- load W transposed: Ws[k][a] = W[a*128 + k] ----
    for (int e = tid; e < D_ * A_; e += THREADS_) {
        int a = e >> 7, k = e & 127;
        s->Ws[k][a] = W[e];
    }
    __syncthreads();

    const int a0 = tn * 8;
    float greg[8], breg[8];
#pragma unroll
    for (int n = 0; n < 8; ++n) {
        greg[n] = gnn[(size_t)b * A_ + a0 + n];
        breg[n] = bias[a0 + n];
    }

    // ==== main loop over M-tiles of pairs ====
    for (int t = 0; t < NTILES; ++t) {
        const int m0 = t * MTILE;
        __syncthreads();   // previous tile's Is reads complete

        // fill Is[k][m] = xs[i][k]*xs[j][k]; lanes take consecutive k ->
        // conflict-free xs reads and Is stores.
        for (int e = tid; e < D_ * (MTILE / 4); e += THREADS_) {
            int k  = e & 127;
            int mq = e >> 7;
            float4 v;
#pragma unroll
            for (int q = 0; q < 4; ++q) {
                int m = m0 + mq * 4 + q;
                float val = 0.f;
                if (m < P_) {
                    unsigned short pr = s->pairs[m];
                    val = s->xs[pr >> 8][k] * s->xs[pr & 255][k];
                }
                reinterpret_cast<float*>(&v)[q] = val;
            }
            *reinterpret_cast<float4*>(&s->Is[k][mq * 4]) = v;
        }
        __syncthreads();

        // register-tiled GEMM, f32x2 packed along a:
        // acc[mi][nj] = {sum for a0+2nj, sum for a0+2nj+1}
        uint64_t acc[4][4];
#pragma unroll
        for (int mi = 0; mi < 4; ++mi)
#pragma unroll
            for (int nj = 0; nj < 4; ++nj) acc[mi][nj] = 0ull;

        const int mrow = tm * 4;
#pragma unroll 2
        for (int k = 0; k < D_; ++k) {
            float4 iv = *reinterpret_cast<const float4*>(&s->Is[k][mrow]);
            ulonglong2 wA = *reinterpret_cast<const ulonglong2*>(&s->Ws[k][a0]);
            ulonglong2 wB = *reinterpret_cast<const ulonglong2*>(&s->Ws[k][a0 + 4]);
            uint64_t w[4] = {wA.x, wA.y, wB.x, wB.y};
            uint64_t im[4];
            PACK_DUP(im[0], iv.x);
            PACK_DUP(im[1], iv.y);
            PACK_DUP(im[2], iv.z);
            PACK_DUP(im[3], iv.w);
#pragma unroll
            for (int mi = 0; mi < 4; ++mi)
#pragma unroll
                for (int nj = 0; nj < 4; ++nj)
                    FMA_F32X2(acc[mi][nj], im[mi], w[nj], acc[mi][nj]);
        }

        // epilogue: bias + relu + dot with gnn -> scores
#pragma unroll
        for (int mi = 0; mi < 4; ++mi) {
            int m = m0 + tm * 4 + mi;
            float sc = 0.f;
            if (m < P_) {
#pragma unroll
                for (int nj = 0; nj < 4; ++nj) {
                    float2 pr = u64_as_f2(acc[mi][nj]);
                    float z0 = fmaxf(pr.x + breg[2 * nj],     0.f);
                    float z1 = fmaxf(pr.y + breg[2 * nj + 1], 0.f);
                    sc = fmaf(greg[2 * nj], z0, sc);
                    sc = fmaf(greg[2 * nj + 1], z1, sc);
                }
            }
            sc += __shfl_xor_sync(0xffffffffu, sc, 16);   // fold the 2 tn's in this warp
            if (lane < 16 && m < P_) atomicAdd(&s->scores[m], sc);
        }
    }
    __syncthreads();

    // ==== softmax over scores[528] ====
    float lmax = -1e30f;
    for (int p = tid; p < P_; p += THREADS_) lmax = fmaxf(lmax, s->scores[p]);
#pragma unroll
    for (int o = 16; o; o >>= 1) lmax = fmaxf(lmax, __shfl_xor_sync(0xffffffffu, lmax, o));
    if (lane == 0) s->red[wid] = lmax;
    __syncthreads();
    if (tid < 32) {
        float v = (tid < 8) ? s->red[tid] : -1e30f;
#pragma unroll
        for (int o = 4; o; o >>= 1) v = fmaxf(v, __shfl_xor_sync(0xffffffffu, v, o));
        if (tid == 0) s->red[8] = v;
    }
    __syncthreads();
    const float mx = s->red[8];

    float lsum = 0.f;
    for (int p = tid; p < P_; p += THREADS_) {
        float e = __expf(s->scores[p] - mx);
        s->scores[p] = e;
        lsum += e;
    }
#pragma unroll
    for (int o = 16; o; o >>= 1) lsum += __shfl_xor_sync(0xffffffffu, lsum, o);
    if (lane == 0) s->red[wid] = lsum;
    __syncthreads();
    if (tid < 32) {
        float v = (tid < 8) ? s->red[tid] : 0.f;
#pragma unroll
        for (int o = 4; o; o >>= 1) v += __shfl_xor_sync(0xffffffffu, v, o);
        if (tid == 0) s->red[9] = v;
    }
    __syncthreads();
    const float scale = 100.f / s->red[9];

    // ==== attn_output[d] = scale * sum_p exp_p * xs[i][d]*xs[j][d] ====
    const int d    = tid & 127;
    const int half = tid >> 7;
    float accd = 0.f;
    const int pstart = half * (P_ / 2);
    for (int p = pstart; p < pstart + P_ / 2; ++p) {
        unsigned short pr = s->pairs[p];
        accd = fmaf(s->scores[p], s->xs[pr >> 8][d] * s->xs[pr & 255][d], accd);
    }
    float* part = reinterpret_cast<float*>(s->Is);   // reuse Is as scratch [2][128]
    part[half * 128 + d] = accd;
    __syncthreads();

    float* outb = out + (size_t)b * (A_ + D_);
    if (tid < 128) {
        outb[tid]       = gnn[(size_t)b * A_ + tid];
        outb[128 + tid] = (part[tid] + part[128 + tid]) * scale;
    }
}

extern "C" void kernel_launch(void* const* d_in, const int* in_sizes, int n_in,
                              void* d_out, int out_size)
{
    const float* gnn  = (const float*)d_in[0];   // [B, 128]
    const float* x    = (const float*)d_in[1];   // [B, 33, 128]
    const float* W    = (const float*)d_in[2];   // [128, 128]
    const float* bias = (const float*)d_in[3];   // [128]
    float* out        = (float*)d_out;           // [B, 256]

    const int B = in_sizes[0] / A_;

    cudaFuncSetAttribute(afm_kernel, cudaFuncAttributeMaxDynamicSharedMemorySize,
                         (int)sizeof(Smem));
    afm_kernel<<<B, THREADS_, sizeof(Smem)>>>(gnn, x, W, bias, out);
}

// round 8
// speedup vs baseline: 3.2784x; 2.1377x over previous
#include <cuda_runtime.h>
#include <cuda_bf16.h>
#include <cstdint>
#include <cstring>

// AFM fused kernel: legacy mma.sync bf16 (3-term split) + fused epilogue.
// One CTA per batch element. B=1024, F=33 (P=528 pairs), D=A=128.

#define F_   33
#define D_   128
#define A_   128
#define P_   528
#define THREADS_ 256
#define MT   128
#define NT_TILES 5
#define SA   136          // bf16 row stride (272B = 68 words; conflict-free)

struct alignas(16) Smem {
    __nv_bfloat16 A_hi[MT * SA];
    __nv_bfloat16 A_lo[MT * SA];
    __nv_bfloat16 W_hi[A_ * SA];
    __nv_bfloat16 W_lo[A_ * SA];
    float xs[F_][132];
    float scores[P_];
    float gnn_s[A_];
    float bias_s[A_];
    float part[256];
    float red[16];
    unsigned short pairs[P_];
};

static __device__ __forceinline__ void mma_bf16(float* c, const uint32_t* a, const uint32_t* b) {
    asm("mma.sync.aligned.m16n8k16.row.col.f32.bf16.bf16.f32 "
        "{%0,%1,%2,%3}, {%4,%5,%6,%7}, {%8,%9}, {%0,%1,%2,%3};"
        : "+f"(c[0]), "+f"(c[1]), "+f"(c[2]), "+f"(c[3])
        : "r"(a[0]), "r"(a[1]), "r"(a[2]), "r"(a[3]), "r"(b[0]), "r"(b[1]));
}

// bf16 hi/lo split of 2 packed floats (packed along k)
static __device__ __forceinline__ void bf16_split2(float a, float b, uint32_t& h, uint32_t& l) {
    __nv_bfloat162 hh = __float22bfloat162_rn(make_float2(a, b));
    float2 hf = __bfloat1622float2(hh);
    __nv_bfloat162 ll = __float22bfloat162_rn(make_float2(a - hf.x, b - hf.y));
    h = *reinterpret_cast<uint32_t*>(&hh);
    l = *reinterpret_cast<uint32_t*>(&ll);
}

__global__ void __launch_bounds__(THREADS_, 1)
afm_kernel(const float* __restrict__ gnn,
           const float* __restrict__ x,
           const float* __restrict__ W,
           const float* __restrict__ bias,
           float* __restrict__ out)
{
    extern __shared__ unsigned char smem_raw[];
    Smem* s = reinterpret_cast<Smem*>(smem_raw);

    const int b    = blockIdx.x;
    const int tid  = threadIdx.x;
    const int lane = tid & 31;
    const int wid  = tid >> 5;
    const int rq   = lane >> 2;        // 0..7  (fragment row)
    const int kq   = 2 * (lane & 3);   // 0,2,4,6 (fragment k/col pair)

    // ---- pair table ----
    for (int p = tid; p < P_; p += THREADS_) {
        int i = 0, base = 0;
        while (base + (F_ - 1 - i) <= p) { base += F_ - 1 - i; ++i; }
        int j = i + 1 + (p - base);
        s->pairs[p] = (unsigned short)((i << 8) | j);
    }
    // ---- x[b] to smem ----
    const float4* xb = reinterpret_cast<const float4*>(x + (size_t)b * F_ * D_);
    for (int e = tid; e < F_ * D_ / 4; e += THREADS_) {
        int f = e >> 5, q = e & 31;
        *reinterpret_cast<float4*>(&s->xs[f][q * 4]) = xb[e];
    }
    if (tid < A_) {
        s->gnn_s[tid]  = gnn[(size_t)b * A_ + tid];
        s->bias_s[tid] = bias[tid];
    }
    // ---- W hi/lo bf16 tiles: W native [a][k], k-contiguous ----
    for (int e = tid; e < A_ * 16; e += THREADS_) {
        int a = e >> 4, kseg = e & 15, k0 = kseg * 8;
        const float4* wp = reinterpret_cast<const float4*>(W + a * D_ + k0);
        float4 w0 = wp[0], w1 = wp[1];
        uint4 hv, lv;
        bf16_split2(w0.x, w0.y, hv.x, lv.x);
        bf16_split2(w0.z, w0.w, hv.y, lv.y);
        bf16_split2(w1.x, w1.y, hv.z, lv.z);
        bf16_split2(w1.z, w1.w, hv.w, lv.w);
        *reinterpret_cast<uint4*>(&s->W_hi[a * SA + k0]) = hv;
        *reinterpret_cast<uint4*>(&s->W_lo[a * SA + k0]) = lv;
    }

    // ==== main loop over 5 M-tiles of 128 pairs ====
    for (int t = 0; t < NT_TILES; ++t) {
        const int m0 = t * MT;
        __syncthreads();   // prior tile's A reads complete (and W/x ready on t=0)

        // ---- fill inner tile hi/lo: A[mloc][k] = xs[i][k]*xs[j][k] ----
        for (int e = tid; e < MT * 16; e += THREADS_) {
            int mloc = e >> 4, kseg = e & 15, k0 = kseg * 8;
            int m = m0 + mloc;
            uint4 hv = make_uint4(0, 0, 0, 0), lv = make_uint4(0, 0, 0, 0);
            if (m < P_) {
                unsigned short pr = s->pairs[m];
                const float4* xi = reinterpret_cast<const float4*>(&s->xs[pr >> 8][k0]);
                const float4* xj = reinterpret_cast<const float4*>(&s->xs[pr & 255][k0]);
                float4 a0 = xi[0], a1 = xi[1], c0 = xj[0], c1 = xj[1];
                bf16_split2(a0.x * c0.x, a0.y * c0.y, hv.x, lv.x);
                bf16_split2(a0.z * c0.z, a0.w * c0.w, hv.y, lv.y);
                bf16_split2(a1.x * c1.x, a1.y * c1.y, hv.z, lv.z);
                bf16_split2(a1.z * c1.z, a1.w * c1.w, hv.w, lv.w);
            }
            *reinterpret_cast<uint4*>(&s->A_hi[mloc * SA + k0]) = hv;
            *reinterpret_cast<uint4*>(&s->A_lo[mloc * SA + k0]) = lv;
        }
        __syncthreads();

        // ---- warp-level GEMM: warp owns 16 rows x full N=128 ----
        float acc[16][4];
#pragma unroll
        for (int j = 0; j < 16; ++j)
#pragma unroll
            for (int q = 0; q < 4; ++q) acc[j][q] = 0.f;

        const int ar = wid * 16 + rq;    // this thread's A row (frag rows ar, ar+8)
#pragma unroll
        for (int ks = 0; ks < 8; ++ks) {
            const int k0 = ks * 16;
            uint32_t ah[4], al[4];
            ah[0] = *reinterpret_cast<const uint32_t*>(&s->A_hi[ar * SA + k0 + kq]);
            ah[1] = *reinterpret_cast<const uint32_t*>(&s->A_hi[(ar + 8) * SA + k0 + kq]);
            ah[2] = *reinterpret_cast<const uint32_t*>(&s->A_hi[ar * SA + k0 + kq + 8]);
            ah[3] = *reinterpret_cast<const uint32_t*>(&s->A_hi[(ar + 8) * SA + k0 + kq + 8]);
            al[0] = *reinterpret_cast<const uint32_t*>(&s->A_lo[ar * SA + k0 + kq]);
            al[1] = *reinterpret_cast<const uint32_t*>(&s->A_lo[(ar + 8) * SA + k0 + kq]);
            al[2] = *reinterpret_cast<const uint32_t*>(&s->A_lo[ar * SA + k0 + kq + 8]);
            al[3] = *reinterpret_cast<const uint32_t*>(&s->A_lo[(ar + 8) * SA + k0 + kq + 8]);
#pragma unroll
            for (int j = 0; j < 16; ++j) {
                const int nr = j * 8 + rq;   // B fragment row (n), lane-dependent
                uint32_t bh[2], bl[2];
                bh[0] = *reinterpret_cast<const uint32_t*>(&s->W_hi[nr * SA + k0 + kq]);
                bh[1] = *reinterpret_cast<const uint32_t*>(&s->W_hi[nr * SA + k0 + kq + 8]);
                bl[0] = *reinterpret_cast<const uint32_t*>(&s->W_lo[nr * SA + k0 + kq]);
                bl[1] = *reinterpret_cast<const uint32_t*>(&s->W_lo[nr * SA + k0 + kq + 8]);
                mma_bf16(acc[j], ah, bh);
                mma_bf16(acc[j], ah, bl);
                mma_bf16(acc[j], al, bh);
            }
        }

        // ---- epilogue: bias + relu + gnn dot, warp-local row reduction ----
        float sc0 = 0.f, sc1 = 0.f;
#pragma unroll
        for (int j = 0; j < 16; ++j) {
            const int n0 = j * 8 + kq;
            float g0 = s->gnn_s[n0], g1 = s->gnn_s[n0 + 1];
            float b0 = s->bias_s[n0], b1 = s->bias_s[n0 + 1];
            sc0 = fmaf(g0, fmaxf(acc[j][0] + b0, 0.f), sc0);
            sc0 = fmaf(g1, fmaxf(acc[j][1] + b1, 0.f), sc0);
            sc1 = fmaf(g0, fmaxf(acc[j][2] + b0, 0.f), sc1);
            sc1 = fmaf(g1, fmaxf(acc[j][3] + b1, 0.f), sc1);
        }
        sc0 += __shfl_xor_sync(0xffffffffu, sc0, 1);
        sc0 += __shfl_xor_sync(0xffffffffu, sc0, 2);
        sc1 += __shfl_xor_sync(0xffffffffu, sc1, 1);
        sc1 += __shfl_xor_sync(0xffffffffu, sc1, 2);
        if ((lane & 3) == 0) {
            int ma = m0 + wid * 16 + rq;
            if (ma < P_)     s->scores[ma]     = sc0;
            if (ma + 8 < P_) s->scores[ma + 8] = sc1;
        }
    }
    __syncthreads();

    // ==== softmax over scores[528] ====
    float lmax = -1e30f;
    for (int p = tid; p < P_; p += THREADS_) lmax = fmaxf(lmax, s->scores[p]);
#pragma unroll
    for (int o = 16; o; o >>= 1) lmax = fmaxf(lmax, __shfl_xor_sync(0xffffffffu, lmax, o));
    if (lane == 0) s->red[wid] = lmax;
    __syncthreads();
    if (tid < 32) {
        float v = (tid < 8) ? s->red[tid] : -1e30f;
#pragma unroll
        for (int o = 4; o; o >>= 1) v = fmaxf(v, __shfl_xor_sync(0xffffffffu, v, o));
        if (tid == 0) s->red[8] = v;
    }
    __syncthreads();
    const float mx = s->red[8];

    float lsum = 0.f;
    for (int p = tid; p < P_; p += THREADS_) {
        float e = __expf(s->scores[p] - mx);
        s->scores[p] = e;
        lsum += e;
    }
#pragma unroll
    for (int o = 16; o; o >>= 1) lsum += __shfl_xor_sync(0xffffffffu, lsum, o);
    if (lane == 0) s->red[wid] = lsum;
    __syncthreads();
    if (tid < 32) {
        float v = (tid < 8) ? s->red[tid] : 0.f;
#pragma unroll
        for (int o = 4; o; o >>= 1) v += __shfl_xor_sync(0xffffffffu, v, o);
        if (tid == 0) s->red[9] = v;
    }
    __syncthreads();
    const float scale = 100.f / s->red[9];

    // ==== attn_output[d] = scale * sum_p exp_p * xs[i][d]*xs[j][d] ====
    const int d    = tid & 127;
    const int half = tid >> 7;
    float accd = 0.f;
    const int pstart = half * (P_ / 2);
    for (int p = pstart; p < pstart + P_ / 2; ++p) {
        unsigned short pr = s->pairs[p];
        accd = fmaf(s->scores[p], s->xs[pr >> 8][d] * s->xs[pr & 255][d], accd);
    }
    s->part[half * 128 + d] = accd;
    __syncthreads();

    float* outb = out + (size_t)b * (A_ + D_);
    if (tid < 128) {
        outb[tid]       = s->gnn_s[tid];
        outb[128 + tid] = (s->part[tid] + s->part[128 + tid]) * scale;
    }
}

extern "C" void kernel_launch(void* const* d_in, const int* in_sizes, int n_in,
                              void* d_out, int out_size)
{
    const float* gnn  = (const float*)d_in[0];   // [B, 128]
    const float* x    = (const float*)d_in[1];   // [B, 33, 128]
    const float* W    = (const float*)d_in[2];   // [128, 128]
    const float* bias = (const float*)d_in[3];   // [128]
    float* out        = (float*)d_out;           // [B, 256]

    const int B = in_sizes[0] / A_;
    const int smem_bytes = (int)sizeof(Smem);

    cudaFuncSetAttribute(afm_kernel, cudaFuncAttributeMaxDynamicSharedMemorySize, smem_bytes);
    afm_kernel<<<B, THREADS_, smem_bytes>>>(gnn, x, W, bias, out);
}

// round 9
// speedup vs baseline: 3.3099x; 1.0096x over previous
#include <cuda_runtime.h>
#include <cuda_bf16.h>
#include <cstdint>
#include <cstring>

// AFM fused kernel: legacy mma.sync bf16 (3-term split) + ldmatrix fragment loads.
// One CTA per batch element. B=1024, F=33 (P=528 pairs), D=A=128.

#define F_   33
#define D_   128
#define A_   128
#define P_   528
#define THREADS_ 256
#define MT   128
#define NT_TILES 5
#define SA   136          // bf16 row stride (272B; LDSM rows hit distinct 16B sub-banks)

struct alignas(16) Smem {
    __nv_bfloat16 A_hi[MT * SA];
    __nv_bfloat16 A_lo[MT * SA];
    __nv_bfloat16 W_hi[A_ * SA];
    __nv_bfloat16 W_lo[A_ * SA];
    float xs[F_][132];
    float scores[P_];
    float gnn_s[A_];
    float bias_s[A_];
    float part[256];
    float red[16];
    unsigned short pairs[P_];
};

static __device__ __forceinline__ uint32_t smem_u32(const void* p) {
    uint32_t a;
    asm("{ .reg .u64 t; cvta.to.shared.u64 t, %1; cvt.u32.u64 %0, t; }" : "=r"(a) : "l"(p));
    return a;
}

#define LDSM_X4(r0, r1, r2, r3, addr) \
    asm volatile("ldmatrix.sync.aligned.m8n8.x4.shared.b16 {%0,%1,%2,%3}, [%4];" \
        : "=r"(r0), "=r"(r1), "=r"(r2), "=r"(r3) : "r"(addr))

static __device__ __forceinline__ void mma_bf16(float* c, const uint32_t* a,
                                                uint32_t b0, uint32_t b1) {
    asm("mma.sync.aligned.m16n8k16.row.col.f32.bf16.bf16.f32 "
        "{%0,%1,%2,%3}, {%4,%5,%6,%7}, {%8,%9}, {%0,%1,%2,%3};"
        : "+f"(c[0]), "+f"(c[1]), "+f"(c[2]), "+f"(c[3])
        : "r"(a[0]), "r"(a[1]), "r"(a[2]), "r"(a[3]), "r"(b0), "r"(b1));
}

// bf16 hi/lo split of 2 packed floats (packed along k)
static __device__ __forceinline__ void bf16_split2(float a, float b, uint32_t& h, uint32_t& l) {
    __nv_bfloat162 hh = __float22bfloat162_rn(make_float2(a, b));
    float2 hf = __bfloat1622float2(hh);
    __nv_bfloat162 ll = __float22bfloat162_rn(make_float2(a - hf.x, b - hf.y));
    h = *reinterpret_cast<uint32_t*>(&hh);
    l = *reinterpret_cast<uint32_t*>(&ll);
}

__global__ void __launch_bounds__(THREADS_, 1)
afm_kernel(const float* __restrict__ gnn,
           const float* __restrict__ x,
           const float* __restrict__ W,
           const float* __restrict__ bias,
           float* __restrict__ out)
{
    extern __shared__ unsigned char smem_raw[];
    Smem* s = reinterpret_cast<Smem*>(smem_raw);

    const int b    = blockIdx.x;
    const int tid  = threadIdx.x;
    const int lane = tid & 31;
    const int wid  = tid >> 5;
    const int rq   = lane >> 2;        // 0..7  (fragment row)
    const int kq   = 2 * (lane & 3);   // 0,2,4,6 (fragment k/col pair)

    // ---- pair table ----
    for (int p = tid; p < P_; p += THREADS_) {
        int i = 0, base = 0;
        while (base + (F_ - 1 - i) <= p) { base += F_ - 1 - i; ++i; }
        int j = i + 1 + (p - base);
        s->pairs[p] = (unsigned short)((i << 8) | j);
    }
    // ---- x[b] to smem ----
    const float4* xb = reinterpret_cast<const float4*>(x + (size_t)b * F_ * D_);
    for (int e = tid; e < F_ * D_ / 4; e += THREADS_) {
        int f = e >> 5, q = e & 31;
        *reinterpret_cast<float4*>(&s->xs[f][q * 4]) = xb[e];
    }
    if (tid < A_) {
        s->gnn_s[tid]  = gnn[(size_t)b * A_ + tid];
        s->bias_s[tid] = bias[tid];
    }
    // ---- W hi/lo bf16 tiles: W native [a][k], k-contiguous ----
    for (int e = tid; e < A_ * 16; e += THREADS_) {
        int a = e >> 4, kseg = e & 15, k0 = kseg * 8;
        const float4* wp = reinterpret_cast<const float4*>(W + a * D_ + k0);
        float4 w0 = wp[0], w1 = wp[1];
        uint4 hv, lv;
        bf16_split2(w0.x, w0.y, hv.x, lv.x);
        bf16_split2(w0.z, w0.w, hv.y, lv.y);
        bf16_split2(w1.x, w1.y, hv.z, lv.z);
        bf16_split2(w1.z, w1.w, hv.w, lv.w);
        *reinterpret_cast<uint4*>(&s->W_hi[a * SA + k0]) = hv;
        *reinterpret_cast<uint4*>(&s->W_lo[a * SA + k0]) = lv;
    }

    // ---- ldmatrix base addresses (byte, per-lane) ----
    // A x4: lanes 0-7 rows 0-7 @k0 | 8-15 rows 8-15 @k0 | 16-23 rows 0-7 @k0+8 | 24-31 rows 8-15 @k0+8
    const int arow = wid * 16 + (lane & 15);
    const int akb  = 8 * (lane >> 4);
    const uint32_t aAhi0 = smem_u32(&s->A_hi[arow * SA + akb]);
    const uint32_t aAlo0 = smem_u32(&s->A_lo[arow * SA + akb]);
    // B x4 (2 n-blocks): lanes 0-7 n 0-7 @k0 | 8-15 n 0-7 @k0+8 | 16-23 n 8-15 @k0 | 24-31 n 8-15 @k0+8
    const int brow = (lane & 7) + 8 * (lane >> 4);
    const int bkb  = 8 * ((lane >> 3) & 1);
    const uint32_t bWhi0 = smem_u32(&s->W_hi[brow * SA + bkb]);
    const uint32_t bWlo0 = smem_u32(&s->W_lo[brow * SA + bkb]);

    // ==== main loop over 5 M-tiles of 128 pairs ====
    for (int t = 0; t < NT_TILES; ++t) {
        const int m0 = t * MT;
        __syncthreads();   // prior tile's A reads complete (and W/x ready on t=0)

        // ---- fill inner tile hi/lo: A[mloc][k] = xs[i][k]*xs[j][k] ----
        for (int e = tid; e < MT * 16; e += THREADS_) {
            int mloc = e >> 4, kseg = e & 15, k0 = kseg * 8;
            int m = m0 + mloc;
            uint4 hv = make_uint4(0, 0, 0, 0), lv = make_uint4(0, 0, 0, 0);
            if (m < P_) {
                unsigned short pr = s->pairs[m];
                const float4* xi = reinterpret_cast<const float4*>(&s->xs[pr >> 8][k0]);
                const float4* xj = reinterpret_cast<const float4*>(&s->xs[pr & 255][k0]);
                float4 a0 = xi[0], a1 = xi[1], c0 = xj[0], c1 = xj[1];
                bf16_split2(a0.x * c0.x, a0.y * c0.y, hv.x, lv.x);
                bf16_split2(a0.z * c0.z, a0.w * c0.w, hv.y, lv.y);
                bf16_split2(a1.x * c1.x, a1.y * c1.y, hv.z, lv.z);
                bf16_split2(a1.z * c1.z, a1.w * c1.w, hv.w, lv.w);
            }
            *reinterpret_cast<uint4*>(&s->A_hi[mloc * SA + k0]) = hv;
            *reinterpret_cast<uint4*>(&s->A_lo[mloc * SA + k0]) = lv;
        }
        __syncthreads();

        // ---- warp-level GEMM: warp owns 16 rows x full N=128 ----
        float acc[16][4];
#pragma unroll
        for (int j = 0; j < 16; ++j)
#pragma unroll
            for (int q = 0; q < 4; ++q) acc[j][q] = 0.f;

#pragma unroll
        for (int ks = 0; ks < 8; ++ks) {
            const uint32_t kb = ks * 32;   // 16 bf16 = 32 bytes
            uint32_t ah[4], al[4];
            LDSM_X4(ah[0], ah[1], ah[2], ah[3], aAhi0 + kb);
            LDSM_X4(al[0], al[1], al[2], al[3], aAlo0 + kb);
#pragma unroll
            for (int jj = 0; jj < 8; ++jj) {
                const uint32_t boff = jj * (16 * SA * 2) + kb;
                uint32_t bh[4], bl[4];
                LDSM_X4(bh[0], bh[1], bh[2], bh[3], bWhi0 + boff);
                LDSM_X4(bl[0], bl[1], bl[2], bl[3], bWlo0 + boff);
                mma_bf16(acc[2 * jj],     ah, bh[0], bh[1]);
                mma_bf16(acc[2 * jj],     ah, bl[0], bl[1]);
                mma_bf16(acc[2 * jj],     al, bh[0], bh[1]);
                mma_bf16(acc[2 * jj + 1], ah, bh[2], bh[3]);
                mma_bf16(acc[2 * jj + 1], ah, bl[2], bl[3]);
                mma_bf16(acc[2 * jj + 1], al, bh[2], bh[3]);
            }
        }

        // ---- epilogue: bias + relu + gnn dot, warp-local row reduction ----
        float sc0 = 0.f, sc1 = 0.f;
#pragma unroll
        for (int j = 0; j < 16; ++j) {
            const int n0 = j * 8 + kq;
            float g0 = s->gnn_s[n0], g1 = s->gnn_s[n0 + 1];
            float b0 = s->bias_s[n0], b1 = s->bias_s[n0 + 1];
            sc0 = fmaf(g0, fmaxf(acc[j][0] + b0, 0.f), sc0);
            sc0 = fmaf(g1, fmaxf(acc[j][1] + b1, 0.f), sc0);
            sc1 = fmaf(g0, fmaxf(acc[j][2] + b0, 0.f), sc1);
            sc1 = fmaf(g1, fmaxf(acc[j][3] + b1, 0.f), sc1);
        }
        sc0 += __shfl_xor_sync(0xffffffffu, sc0, 1);
        sc0 += __shfl_xor_sync(0xffffffffu, sc0, 2);
        sc1 += __shfl_xor_sync(0xffffffffu, sc1, 1);
        sc1 += __shfl_xor_sync(0xffffffffu, sc1, 2);
        if ((lane & 3) == 0) {
            int ma = m0 + wid * 16 + rq;
            if (ma < P_)     s->scores[ma]     = sc0;
            if (ma + 8 < P_) s->scores[ma + 8] = sc1;
        }
    }
    __syncthreads();

    // ==== softmax over scores[528] ====
    float lmax = -1e30f;
    for (int p = tid; p < P_; p += THREADS_) lmax = fmaxf(lmax, s->scores[p]);
#pragma unroll
    for (int o = 16; o; o >>= 1) lmax = fmaxf(lmax, __shfl_xor_sync(0xffffffffu, lmax, o));
    if (lane == 0) s->red[wid] = lmax;
    __syncthreads();
    if (tid < 32) {
        float v = (tid < 8) ? s->red[tid] : -1e30f;
#pragma unroll
        for (int o = 4; o; o >>= 1) v = fmaxf(v, __shfl_xor_sync(0xffffffffu, v, o));
        if (tid == 0) s->red[8] = v;
    }
    __syncthreads();
    const float mx = s->red[8];

    float lsum = 0.f;
    for (int p = tid; p < P_; p += THREADS_) {
        float e = __expf(s->scores[p] - mx);
        s->scores[p] = e;
        lsum += e;
    }
#pragma unroll
    for (int o = 16; o; o >>= 1) lsum += __shfl_xor_sync(0xffffffffu, lsum, o);
    if (lane == 0) s->red[wid] = lsum;
    __syncthreads();
    if (tid < 32) {
        float v = (tid < 8) ? s->red[tid] : 0.f;
#pragma unroll
        for (int o = 4; o; o >>= 1) v += __shfl_xor_sync(0xffffffffu, v, o);
        if (tid == 0) s->red[9] = v;
    }
    __syncthreads();
    const float scale = 100.f / s->red[9];

    // ==== attn_output[d] = scale * sum_p exp_p * xs[i][d]*xs[j][d] ====
    const int d    = tid & 127;
    const int half = tid >> 7;
    float accd = 0.f;
    const int pstart = half * (P_ / 2);
    for (int p = pstart; p < pstart + P_ / 2; ++p) {
        unsigned short pr = s->pairs[p];
        accd = fmaf(s->scores[p], s->xs[pr >> 8][d] * s->xs[pr & 255][d], accd);
    }
    s->part[half * 128 + d] = accd;
    __syncthreads();

    float* outb = out + (size_t)b * (A_ + D_);
    if (tid < 128) {
        outb[tid]       = s->gnn_s[tid];
        outb[128 + tid] = (s->part[tid] + s->part[128 + tid]) * scale;
    }
}

extern "C" void kernel_launch(void* const* d_in, const int* in_sizes, int n_in,
                              void* d_out, int out_size)
{
    const float* gnn  = (const float*)d_in[0];   // [B, 128]
    const float* x    = (const float*)d_in[1];   // [B, 33, 128]
    const float* W    = (const float*)d_in[2];   // [128, 128]
    const float* bias = (const float*)d_in[3];   // [128]
    float* out        = (float*)d_out;           // [B, 256]

    const int B = in_sizes[0] / A_;
    const int smem_bytes = (int)sizeof(Smem);

    cudaFuncSetAttribute(afm_kernel, cudaFuncAttributeMaxDynamicSharedMemorySize, smem_bytes);
    afm_kernel<<<B, THREADS_, smem_bytes>>>(gnn, x, W, bias, out);
}

// round 11
// speedup vs baseline: 3.3292x; 1.0059x over previous
#include <cuda_runtime.h>
#include <cuda_bf16.h>
#include <cstdint>
#include <cstring>

// AFM fused kernel: legacy mma.sync bf16 (3-term split), 512 threads (16 warps).
// One CTA per batch element. B=1024, F=33 (P=528 pairs), D=A=128.

#define F_   33
#define D_   128
#define A_   128
#define P_   528
#define THREADS_ 512
#define MT   128
#define NT_TILES 5
#define SA   136          // bf16 row stride (272B; LDSM rows hit distinct 16B sub-banks)

struct alignas(16) Smem {
    __nv_bfloat16 A_hi[MT * SA];
    __nv_bfloat16 A_lo[MT * SA];
    __nv_bfloat16 W_hi[A_ * SA];
    __nv_bfloat16 W_lo[A_ * SA];
    float xs[F_][132];
    float scores[P_];
    float gnn_s[A_];
    float bias_s[A_];
    float part[512];
    float red[32];
    unsigned short pairs[P_];
};

static __device__ __forceinline__ uint32_t smem_u32(const void* p) {
    uint32_t a;
    asm("{ .reg .u64 t; cvta.to.shared.u64 t, %1; cvt.u32.u64 %0, t; }" : "=r"(a) : "l"(p));
    return a;
}

#define LDSM_X4(r0, r1, r2, r3, addr) \
    asm volatile("ldmatrix.sync.aligned.m8n8.x4.shared.b16 {%0,%1,%2,%3}, [%4];" \
        : "=r"(r0), "=r"(r1), "=r"(r2), "=r"(r3) : "r"(addr))

static __device__ __forceinline__ void mma_bf16(float* c, const uint32_t* a,
                                                uint32_t b0, uint32_t b1) {
    asm("mma.sync.aligned.m16n8k16.row.col.f32.bf16.bf16.f32 "
        "{%0,%1,%2,%3}, {%4,%5,%6,%7}, {%8,%9}, {%0,%1,%2,%3};"
        : "+f"(c[0]), "+f"(c[1]), "+f"(c[2]), "+f"(c[3])
        : "r"(a[0]), "r"(a[1]), "r"(a[2]), "r"(a[3]), "r"(b0), "r"(b1));
}

// bf16 hi/lo split of 2 packed floats (packed along k)
static __device__ __forceinline__ void bf16_split2(float a, float b, uint32_t& h, uint32_t& l) {
    __nv_bfloat162 hh = __float22bfloat162_rn(make_float2(a, b));
    float2 hf = __bfloat1622float2(hh);
    __nv_bfloat162 ll = __float22bfloat162_rn(make_float2(a - hf.x, b - hf.y));
    h = *reinterpret_cast<uint32_t*>(&hh);
    l = *reinterpret_cast<uint32_t*>(&ll);
}

__global__ void __launch_bounds__(THREADS_, 1)
afm_kernel(const float* __restrict__ gnn,
           const float* __restrict__ x,
           const float* __restrict__ W,
           const float* __restrict__ bias,
           float* __restrict__ out)
{
    extern __shared__ unsigned char smem_raw[];
    Smem* s = reinterpret_cast<Smem*>(smem_raw);

    const int b    = blockIdx.x;
    const int tid  = threadIdx.x;
    const int lane = tid & 31;
    const int wid  = tid >> 5;         // 0..15
    const int mi   = wid & 7;          // m-subtile (16 rows)
    const int nh   = wid >> 3;         // n-half (64 cols)
    const int rq   = lane >> 2;        // 0..7  (fragment row)
    const int kq   = 2 * (lane & 3);   // 0,2,4,6 (fragment col pair)

    // ---- pair table + zero scores ----
    for (int p = tid; p < P_; p += THREADS_) {
        int i = 0, base = 0;
        while (base + (F_ - 1 - i) <= p) { base += F_ - 1 - i; ++i; }
        int j = i + 1 + (p - base);
        s->pairs[p] = (unsigned short)((i << 8) | j);
        s->scores[p] = 0.f;
    }
    // ---- x[b] to smem ----
    const float4* xb = reinterpret_cast<const float4*>(x + (size_t)b * F_ * D_);
    for (int e = tid; e < F_ * D_ / 4; e += THREADS_) {
        int f = e >> 5, q = e & 31;
        *reinterpret_cast<float4*>(&s->xs[f][q * 4]) = xb[e];
    }
    if (tid < A_) {
        s->gnn_s[tid]  = gnn[(size_t)b * A_ + tid];
        s->bias_s[tid] = bias[tid];
    }
    // ---- W hi/lo bf16 tiles: W native [a][k], k-contiguous ----
    for (int e = tid; e < A_ * 16; e += THREADS_) {
        int a = e >> 4, kseg = e & 15, k0 = kseg * 8;
        const float4* wp = reinterpret_cast<const float4*>(W + a * D_ + k0);
        float4 w0 = wp[0], w1 = wp[1];
        uint4 hv, lv;
        bf16_split2(w0.x, w0.y, hv.x, lv.x);
        bf16_split2(w0.z, w0.w, hv.y, lv.y);
        bf16_split2(w1.x, w1.y, hv.z, lv.z);
        bf16_split2(w1.z, w1.w, hv.w, lv.w);
        *reinterpret_cast<uint4*>(&s->W_hi[a * SA + k0]) = hv;
        *reinterpret_cast<uint4*>(&s->W_lo[a * SA + k0]) = lv;
    }

    // ---- ldmatrix base addresses (byte, per-lane) ----
    const int arow = mi * 16 + (lane & 15);
    const int akb  = 8 * (lane >> 4);
    const uint32_t aAhi0 = smem_u32(&s->A_hi[arow * SA + akb]);
    const uint32_t aAlo0 = smem_u32(&s->A_lo[arow * SA + akb]);
    const int brow = nh * 64 + (lane & 7) + 8 * (lane >> 4);
    const int bkb  = 8 * ((lane >> 3) & 1);
    const uint32_t bWhi0 = smem_u32(&s->W_hi[brow * SA + bkb]);
    const uint32_t bWlo0 = smem_u32(&s->W_lo[brow * SA + bkb]);

    // ==== main loop over 5 M-tiles of 128 pairs ====
    for (int t = 0; t < NT_TILES; ++t) {
        const int m0 = t * MT;
        __syncthreads();   // prior tile's A reads complete (and init done on t=0)

        // ---- fill inner tile hi/lo: A[mloc][k] = xs[i][k]*xs[j][k] ----
        for (int e = tid; e < MT * 16; e += THREADS_) {
            int mloc = e >> 4, kseg = e & 15, k0 = kseg * 8;
            int m = m0 + mloc;
            uint4 hv = make_uint4(0, 0, 0, 0), lv = make_uint4(0, 0, 0, 0);
            if (m < P_) {
                unsigned short pr = s->pairs[m];
                const float4* xi = reinterpret_cast<const float4*>(&s->xs[pr >> 8][k0]);
                const float4* xj = reinterpret_cast<const float4*>(&s->xs[pr & 255][k0]);
                float4 a0 = xi[0], a1 = xi[1], c0 = xj[0], c1 = xj[1];
                bf16_split2(a0.x * c0.x, a0.y * c0.y, hv.x, lv.x);
                bf16_split2(a0.z * c0.z, a0.w * c0.w, hv.y, lv.y);
                bf16_split2(a1.x * c1.x, a1.y * c1.y, hv.z, lv.z);
                bf16_split2(a1.z * c1.z, a1.w * c1.w, hv.w, lv.w);
            }
            *reinterpret_cast<uint4*>(&s->A_hi[mloc * SA + k0]) = hv;
            *reinterpret_cast<uint4*>(&s->A_lo[mloc * SA + k0]) = lv;
        }
        __syncthreads();

        // ---- warp-level GEMM: warp owns 16 rows x 64 cols ----
        float acc[8][4];
#pragma unroll
        for (int j = 0; j < 8; ++j)
#pragma unroll
            for (int q = 0; q < 4; ++q) acc[j][q] = 0.f;

#pragma unroll
        for (int ks = 0; ks < 8; ++ks) {
            const uint32_t kb = ks * 32;   // 16 bf16 = 32 bytes
            uint32_t ah[4], al[4];
            LDSM_X4(ah[0], ah[1], ah[2], ah[3], aAhi0 + kb);
            LDSM_X4(al[0], al[1], al[2], al[3], aAlo0 + kb);
#pragma unroll
            for (int jj = 0; jj < 4; ++jj) {
                const uint32_t boff = jj * (16 * SA * 2) + kb;
                uint32_t bh[4], bl[4];
                LDSM_X4(bh[0], bh[1], bh[2], bh[3], bWhi0 + boff);
                LDSM_X4(bl[0], bl[1], bl[2], bl[3], bWlo0 + boff);
                mma_bf16(acc[2 * jj],     ah, bh[0], bh[1]);
                mma_bf16(acc[2 * jj],     ah, bl[0], bl[1]);
                mma_bf16(acc[2 * jj],     al, bh[0], bh[1]);
                mma_bf16(acc[2 * jj + 1], ah, bh[2], bh[3]);
                mma_bf16(acc[2 * jj + 1], ah, bl[2], bl[3]);
                mma_bf16(acc[2 * jj + 1], al, bh[2], bh[3]);
            }
        }

        // ---- epilogue: bias + relu + gnn dot over this warp's 64 cols ----
        float sc0 = 0.f, sc1 = 0.f;
#pragma unroll
        for (int j = 0; j < 8; ++j) {
            const int n0 = nh * 64 + j * 8 + kq;
            float g0 = s->gnn_s[n0], g1 = s->gnn_s[n0 + 1];
            float b0 = s->bias_s[n0], b1 = s->bias_s[n0 + 1];
            sc0 = fmaf(g0, fmaxf(acc[j][0] + b0, 0.f), sc0);
            sc0 = fmaf(g1, fmaxf(acc[j][1] + b1, 0.f), sc0);
            sc1 = fmaf(g0, fmaxf(acc[j][2] + b0, 0.f), sc1);
            sc1 = fmaf(g1, fmaxf(acc[j][3] + b1, 0.f), sc1);
        }
        sc0 += __shfl_xor_sync(0xffffffffu, sc0, 1);
        sc0 += __shfl_xor_sync(0xffffffffu, sc0, 2);
        sc1 += __shfl_xor_sync(0xffffffffu, sc1, 1);
        sc1 += __shfl_xor_sync(0xffffffffu, sc1, 2);
        if ((lane & 3) == 0) {
            int ma = m0 + mi * 16 + rq;       // two warps (nh=0/1) add halves
            if (ma < P_)     atomicAdd(&s->scores[ma],     sc0);
            if (ma + 8 < P_) atomicAdd(&s->scores[ma + 8], sc1);
        }
    }
    __syncthreads();

    // ==== softmax over scores[528] ====
    float lmax = -1e30f;
    for (int p = tid; p < P_; p += THREADS_) lmax = fmaxf(lmax, s->scores[p]);
#pragma unroll
    for (int o = 16; o; o >>= 1) lmax = fmaxf(lmax, __shfl_xor_sync(0xffffffffu, lmax, o));
    if (lane == 0) s->red[wid] = lmax;
    __syncthreads();
    if (tid < 32) {
        float v = (tid < 16) ? s->red[tid] : -1e30f;
#pragma unroll
        for (int o = 8; o; o >>= 1) v = fmaxf(v, __shfl_xor_sync(0xffffffffu, v, o));
        if (tid == 0) s->red[16] = v;
    }
    __syncthreads();
    const float mx = s->red[16];

    float lsum = 0.f;
    for (int p = tid; p < P_; p += THREADS_) {
        float e = __expf(s->scores[p] - mx);
        s->scores[p] = e;
        lsum += e;
    }
#pragma unroll
    for (int o = 16; o; o >>= 1) lsum += __shfl_xor_sync(0xffffffffu, lsum, o);
    if (lane == 0) s->red[wid] = lsum;
    __syncthreads();
    if (tid < 32) {
        float v = (tid < 16) ? s->red[tid] : 0.f;
#pragma unroll
        for (int o = 8; o; o >>= 1) v += __shfl_xor_sync(0xffffffffu, v, o);
        if (tid == 0) s->red[17] = v;
    }
    __syncthreads();
    const float scale = 100.f / s->red[17];

    // ==== attn_output[d] = scale * sum_p exp_p * xs[i][d]*xs[j][d] ====
    const int d  = tid & 127;
    const int qt = tid >> 7;               // 4 quarters of the pair range
    float accd = 0.f;
    const int pstart = qt * (P_ / 4);
    for (int p = pstart; p < pstart + P_ / 4; ++p) {
        unsigned short pr = s->pairs[p];
        accd = fmaf(s->scores[p], s->xs[pr >> 8][d] * s->xs[pr & 255][d], accd);
    }
    s->part[qt * 128 + d] = accd;
    __syncthreads();

    float* outb = out + (size_t)b * (A_ + D_);
    if (tid < 128) {
        outb[tid] = s->gnn_s[tid];
    } else if (tid < 256) {
        int dd = tid - 128;
        outb[128 + dd] = (s->part[dd] + s->part[128 + dd] + s->part[256 + dd] + s->part[384 + dd]) * scale;
    }
}

extern "C" void kernel_launch(void* const* d_in, const int* in_sizes, int n_in,
                              void* d_out, int out_size)
{
    const float* gnn  = (const float*)d_in[0];   // [B, 128]
    const float* x    = (const float*)d_in[1];   // [B, 33, 128]
    const float* W    = (const float*)d_in[2];   // [128, 128]
    const float* bias = (const float*)d_in[3];   // [128]
    float* out        = (float*)d_out;           // [B, 256]

    const int B = in_sizes[0] / A_;
    const int smem_bytes = (int)sizeof(Smem);

    cudaFuncSetAttribute(afm_kernel, cudaFuncAttributeMaxDynamicSharedMemorySize, smem_bytes);
    afm_kernel<<<B, THREADS_, smem_bytes>>>(gnn, x, W, bias, out);
}

// round 12
// speedup vs baseline: 3.3841x; 1.0165x over previous
#include <cuda_runtime.h>
#include <cuda_bf16.h>
#include <cstdint>
#include <cstring>

// AFM fused kernel: legacy mma.sync bf16 (3-term split), 512 threads,
// 4x4 warp grid (32m x 32n per warp) to balance LDSM traffic.
// One CTA per batch element. B=1024, F=33 (P=528 pairs), D=A=128.

#define F_   33
#define D_   128
#define A_   128
#define P_   528
#define THREADS_ 512
#define MT   128
#define NT_TILES 5
#define SA   136          // bf16 row stride (272B; LDSM rows hit distinct 16B sub-banks)

struct alignas(16) Smem {
    __nv_bfloat16 A_hi[MT * SA];
    __nv_bfloat16 A_lo[MT * SA];
    __nv_bfloat16 W_hi[A_ * SA];
    __nv_bfloat16 W_lo[A_ * SA];
    float xs[F_][132];
    float scores[P_];
    float gnn_s[A_];
    float bias_s[A_];
    float part[512];
    float red[32];
    unsigned short pairs[P_];
};

static __device__ __forceinline__ uint32_t smem_u32(const void* p) {
    uint32_t a;
    asm("{ .reg .u64 t; cvta.to.shared.u64 t, %1; cvt.u32.u64 %0, t; }" : "=r"(a) : "l"(p));
    return a;
}

#define LDSM_X4(r0, r1, r2, r3, addr) \
    asm volatile("ldmatrix.sync.aligned.m8n8.x4.shared.b16 {%0,%1,%2,%3}, [%4];" \
        : "=r"(r0), "=r"(r1), "=r"(r2), "=r"(r3) : "r"(addr))

static __device__ __forceinline__ void mma_bf16(float* c, const uint32_t* a,
                                                uint32_t b0, uint32_t b1) {
    asm("mma.sync.aligned.m16n8k16.row.col.f32.bf16.bf16.f32 "
        "{%0,%1,%2,%3}, {%4,%5,%6,%7}, {%8,%9}, {%0,%1,%2,%3};"
        : "+f"(c[0]), "+f"(c[1]), "+f"(c[2]), "+f"(c[3])
        : "r"(a[0]), "r"(a[1]), "r"(a[2]), "r"(a[3]), "r"(b0), "r"(b1));
}

// bf16 hi/lo split of 2 packed floats (packed along k)
static __device__ __forceinline__ void bf16_split2(float a, float b, uint32_t& h, uint32_t& l) {
    __nv_bfloat162 hh = __float22bfloat162_rn(make_float2(a, b));
    float2 hf = __bfloat1622float2(hh);
    __nv_bfloat162 ll = __float22bfloat162_rn(make_float2(a - hf.x, b - hf.y));
    h = *reinterpret_cast<uint32_t*>(&hh);
    l = *reinterpret_cast<uint32_t*>(&ll);
}

__global__ void __launch_bounds__(THREADS_, 1)
afm_kernel(const float* __restrict__ gnn,
           const float* __restrict__ x,
           const float* __restrict__ W,
           const float* __restrict__ bias,
           float* __restrict__ out)
{
    extern __shared__ unsigned char smem_raw[];
    Smem* s = reinterpret_cast<Smem*>(smem_raw);

    const int b    = blockIdx.x;
    const int tid  = threadIdx.x;
    const int lane = tid & 31;
    const int wid  = tid >> 5;         // 0..15
    const int mi   = wid & 3;          // m-subtile (32 rows)
    const int ni   = wid >> 2;         // n-subtile (32 cols)
    const int rq   = lane >> 2;        // 0..7  (fragment row)
    const int kq   = 2 * (lane & 3);   // 0,2,4,6 (fragment col pair)

    // ---- pair table + zero scores ----
    for (int p = tid; p < P_; p += THREADS_) {
        int i = 0, base = 0;
        while (base + (F_ - 1 - i) <= p) { base += F_ - 1 - i; ++i; }
        int j = i + 1 + (p - base);
        s->pairs[p] = (unsigned short)((i << 8) | j);
        s->scores[p] = 0.f;
    }
    // ---- x[b] to smem ----
    const float4* xb = reinterpret_cast<const float4*>(x + (size_t)b * F_ * D_);
    for (int e = tid; e < F_ * D_ / 4; e += THREADS_) {
        int f = e >> 5, q = e & 31;
        *reinterpret_cast<float4*>(&s->xs[f][q * 4]) = xb[e];
    }
    if (tid < A_) {
        s->gnn_s[tid]  = gnn[(size_t)b * A_ + tid];
        s->bias_s[tid] = bias[tid];
    }
    // ---- W hi/lo bf16 tiles: W native [a][k], k-contiguous ----
    for (int e = tid; e < A_ * 16; e += THREADS_) {
        int a = e >> 4, kseg = e & 15, k0 = kseg * 8;
        const float4* wp = reinterpret_cast<const float4*>(W + a * D_ + k0);
        float4 w0 = wp[0], w1 = wp[1];
        uint4 hv, lv;
        bf16_split2(w0.x, w0.y, hv.x, lv.x);
        bf16_split2(w0.z, w0.w, hv.y, lv.y);
        bf16_split2(w1.x, w1.y, hv.z, lv.z);
        bf16_split2(w1.z, w1.w, hv.w, lv.w);
        *reinterpret_cast<uint4*>(&s->W_hi[a * SA + k0]) = hv;
        *reinterpret_cast<uint4*>(&s->W_lo[a * SA + k0]) = lv;
    }

    // ---- ldmatrix base addresses (byte, per-lane) ----
    // A x4 covers 16m x 16k: lanes 0-7 rows+0..7 @k0 | 8-15 rows+8..15 @k0
    //                      | 16-23 rows+0..7 @k0+8 | 24-31 rows+8..15 @k0+8
    const int arow = mi * 32 + (lane & 15);
    const int akb  = 8 * (lane >> 4);
    const uint32_t aAhi0 = smem_u32(&s->A_hi[arow * SA + akb]);
    const uint32_t aAlo0 = smem_u32(&s->A_lo[arow * SA + akb]);
    const uint32_t ASTEP = 16 * SA * 2;   // +16 rows, bytes
    // B x4 covers 16n x 16k: lanes 0-7 n+0..7 @k0 | 8-15 n+0..7 @k0+8
    //                      | 16-23 n+8..15 @k0 | 24-31 n+8..15 @k0+8
    const int brow = ni * 32 + (lane & 7) + 8 * (lane >> 4);
    const int bkb  = 8 * ((lane >> 3) & 1);
    const uint32_t bWhi0 = smem_u32(&s->W_hi[brow * SA + bkb]);
    const uint32_t bWlo0 = smem_u32(&s->W_lo[brow * SA + bkb]);

    // ==== main loop over 5 M-tiles of 128 pairs ====
    for (int t = 0; t < NT_TILES; ++t) {
        const int m0 = t * MT;
        __syncthreads();   // prior tile's A reads complete (and init done on t=0)

        // ---- fill inner tile hi/lo: A[mloc][k] = xs[i][k]*xs[j][k] ----
        for (int e = tid; e < MT * 16; e += THREADS_) {
            int mloc = e >> 4, kseg = e & 15, k0 = kseg * 8;
            int m = m0 + mloc;
            uint4 hv = make_uint4(0, 0, 0, 0), lv = make_uint4(0, 0, 0, 0);
            if (m < P_) {
                unsigned short pr = s->pairs[m];
                const float4* xi = reinterpret_cast<const float4*>(&s->xs[pr >> 8][k0]);
                const float4* xj = reinterpret_cast<const float4*>(&s->xs[pr & 255][k0]);
                float4 a0 = xi[0], a1 = xi[1], c0 = xj[0], c1 = xj[1];
                bf16_split2(a0.x * c0.x, a0.y * c0.y, hv.x, lv.x);
                bf16_split2(a0.z * c0.z, a0.w * c0.w, hv.y, lv.y);
                bf16_split2(a1.x * c1.x, a1.y * c1.y, hv.z, lv.z);
                bf16_split2(a1.z * c1.z, a1.w * c1.w, hv.w, lv.w);
            }
            *reinterpret_cast<uint4*>(&s->A_hi[mloc * SA + k0]) = hv;
            *reinterpret_cast<uint4*>(&s->A_lo[mloc * SA + k0]) = lv;
        }
        __syncthreads();

        // ---- warp-level GEMM: warp owns 32 rows x 32 cols ----
        float acc[2][4][4];   // [m-frag][n-frag][quad]
#pragma unroll
        for (int mf = 0; mf < 2; ++mf)
#pragma unroll
            for (int nf = 0; nf < 4; ++nf)
#pragma unroll
                for (int q = 0; q < 4; ++q) acc[mf][nf][q] = 0.f;

#pragma unroll
        for (int ks = 0; ks < 8; ++ks) {
            const uint32_t kb = ks * 32;   // 16 bf16 = 32 bytes
            uint32_t ah[2][4], al[2][4], bh[2][4], bl[2][4];
            LDSM_X4(ah[0][0], ah[0][1], ah[0][2], ah[0][3], aAhi0 + kb);
            LDSM_X4(ah[1][0], ah[1][1], ah[1][2], ah[1][3], aAhi0 + ASTEP + kb);
            LDSM_X4(al[0][0], al[0][1], al[0][2], al[0][3], aAlo0 + kb);
            LDSM_X4(al[1][0], al[1][1], al[1][2], al[1][3], aAlo0 + ASTEP + kb);
            LDSM_X4(bh[0][0], bh[0][1], bh[0][2], bh[0][3], bWhi0 + kb);
            LDSM_X4(bh[1][0], bh[1][1], bh[1][2], bh[1][3], bWhi0 + ASTEP + kb);
            LDSM_X4(bl[0][0], bl[0][1], bl[0][2], bl[0][3], bWlo0 + kb);
            LDSM_X4(bl[1][0], bl[1][1], bl[1][2], bl[1][3], bWlo0 + ASTEP + kb);
#pragma unroll
            for (int mf = 0; mf < 2; ++mf)
#pragma unroll
                for (int jn = 0; jn < 2; ++jn) {
                    mma_bf16(acc[mf][2 * jn],     ah[mf], bh[jn][0], bh[jn][1]);
                    mma_bf16(acc[mf][2 * jn],     ah[mf], bl[jn][0], bl[jn][1]);
                    mma_bf16(acc[mf][2 * jn],     al[mf], bh[jn][0], bh[jn][1]);
                    mma_bf16(acc[mf][2 * jn + 1], ah[mf], bh[jn][2], bh[jn][3]);
                    mma_bf16(acc[mf][2 * jn + 1], ah[mf], bl[jn][2], bl[jn][3]);
                    mma_bf16(acc[mf][2 * jn + 1], al[mf], bh[jn][2], bh[jn][3]);
                }
        }

        // ---- epilogue: bias + relu + gnn dot over this warp's 32 cols ----
        // thread rows: mi*32 + mf*16 + rq + 8*h  (h = q>>1); cols: ni*32 + nf*8 + kq + (q&1)
#pragma unroll
        for (int mf = 0; mf < 2; ++mf) {
            float sc0 = 0.f, sc1 = 0.f;
#pragma unroll
            for (int nf = 0; nf < 4; ++nf) {
                const int n0 = ni * 32 + nf * 8 + kq;
                float g0 = s->gnn_s[n0], g1 = s->gnn_s[n0 + 1];
                float b0 = s->bias_s[n0], b1 = s->bias_s[n0 + 1];
                sc0 = fmaf(g0, fmaxf(acc[mf][nf][0] + b0, 0.f), sc0);
                sc0 = fmaf(g1, fmaxf(acc[mf][nf][1] + b1, 0.f), sc0);
                sc1 = fmaf(g0, fmaxf(acc[mf][nf][2] + b0, 0.f), sc1);
                sc1 = fmaf(g1, fmaxf(acc[mf][nf][3] + b1, 0.f), sc1);
            }
            sc0 += __shfl_xor_sync(0xffffffffu, sc0, 1);
            sc0 += __shfl_xor_sync(0xffffffffu, sc0, 2);
            sc1 += __shfl_xor_sync(0xffffffffu, sc1, 1);
            sc1 += __shfl_xor_sync(0xffffffffu, sc1, 2);
            if ((lane & 3) == 0) {
                int ma = m0 + mi * 32 + mf * 16 + rq;   // 4 n-warps add per row
                if (ma < P_)     atomicAdd(&s->scores[ma],     sc0);
                if (ma + 8 < P_) atomicAdd(&s->scores[ma + 8], sc1);
            }
        }
    }
    __syncthreads();

    // ==== softmax over scores[528] ====
    float lmax = -1e30f;
    for (int p = tid; p < P_; p += THREADS_) lmax = fmaxf(lmax, s->scores[p]);
#pragma unroll
    for (int o = 16; o; o >>= 1) lmax = fmaxf(lmax, __shfl_xor_sync(0xffffffffu, lmax, o));
    if (lane == 0) s->red[wid] = lmax;
    __syncthreads();
    if (tid < 32) {
        float v = (tid < 16) ? s->red[tid] : -1e30f;
#pragma unroll
        for (int o = 8; o; o >>= 1) v = fmaxf(v, __shfl_xor_sync(0xffffffffu, v, o));
        if (tid == 0) s->red[16] = v;
    }
    __syncthreads();
    const float mx = s->red[16];

    float lsum = 0.f;
    for (int p = tid; p < P_; p += THREADS_) {
        float e = __expf(s->scores[p] - mx);
        s->scores[p] = e;
        lsum += e;
    }
#pragma unroll
    for (int o = 16; o; o >>= 1) lsum += __shfl_xor_sync(0xffffffffu, lsum, o);
    if (lane == 0) s->red[wid] = lsum;
    __syncthreads();
    if (tid < 32) {
        float v = (tid < 16) ? s->red[tid] : 0.f;
#pragma unroll
        for (int o = 8; o; o >>= 1) v += __shfl_xor_sync(0xffffffffu, v, o);
        if (tid == 0) s->red[17] = v;
    }
    __syncthreads();
    const float scale = 100.f / s->red[17];

    // ==== attn_output[d] = scale * sum_p exp_p * xs[i][d]*xs[j][d] ====
    const int d  = tid & 127;
    const int qt = tid >> 7;               // 4 quarters of the pair range
    float accd = 0.f;
    const int pstart = qt * (P_ / 4);
    for (int p = pstart; p < pstart + P_ / 4; ++p) {
        unsigned short pr = s->pairs[p];
        accd = fmaf(s->scores[p], s->xs[pr >> 8][d] * s->xs[pr & 255][d], accd);
    }
    s->part[qt * 128 + d] = accd;
    __syncthreads();

    float* outb = out + (size_t)b * (A_ + D_);
    if (tid < 128) {
        outb[tid] = s->gnn_s[tid];
    } else if (tid < 256) {
        int dd = tid - 128;
        outb[128 + dd] = (s->part[dd] + s->part[128 + dd] + s->part[256 + dd] + s->part[384 + dd]) * scale;
    }
}

extern "C" void kernel_launch(void* const* d_in, const int* in_sizes, int n_in,
                              void* d_out, int out_size)
{
    const float* gnn  = (const float*)d_in[0];   // [B, 128]
    const float* x    = (const float*)d_in[1];   // [B, 33, 128]
    const float* W    = (const float*)d_in[2];   // [128, 128]
    const float* bias = (const float*)d_in[3];   // [128]
    float* out        = (float*)d_out;           // [B, 256]

    const int B = in_sizes[0] / A_;
    const int smem_bytes = (int)sizeof(Smem);

    cudaFuncSetAttribute(afm_kernel, cudaFuncAttributeMaxDynamicSharedMemorySize, smem_bytes);
    afm_kernel<<<B, THREADS_, smem_bytes>>>(gnn, x, W, bias, out);
}

// round 13
// speedup vs baseline: 3.7391x; 1.1049x over previous
#include <cuda_runtime.h>
#include <cuda_bf16.h>
#include <cstdint>
#include <cstring>

// AFM fused kernel: legacy mma.sync bf16 (3-term split), 256 threads,
// 2 CTAs/SM for cross-CTA phase overlap. MT=32 (17 tiles), smem ~107KB.
// One CTA per batch element. B=1024, F=33 (P=528 pairs), D=A=128.

#define F_   33
#define D_   128
#define A_   128
#define P_   528
#define THREADS_ 256
#define MT   32
#define NT_TILES 17
#define SA   136          // bf16 row stride (272B; LDSM rows hit distinct 16B sub-banks)

struct alignas(16) Smem {
    __nv_bfloat16 A_hi[MT * SA];
    __nv_bfloat16 A_lo[MT * SA];
    __nv_bfloat16 W_hi[A_ * SA];
    __nv_bfloat16 W_lo[A_ * SA];
    float xs[F_][132];
    float scores[P_];
    float gnn_s[A_];
    float bias_s[A_];
    float part[256];
    float red[16];
    unsigned short pairs[P_];
};

static __device__ __forceinline__ uint32_t smem_u32(const void* p) {
    uint32_t a;
    asm("{ .reg .u64 t; cvta.to.shared.u64 t, %1; cvt.u32.u64 %0, t; }" : "=r"(a) : "l"(p));
    return a;
}

#define LDSM_X4(r0, r1, r2, r3, addr) \
    asm volatile("ldmatrix.sync.aligned.m8n8.x4.shared.b16 {%0,%1,%2,%3}, [%4];" \
        : "=r"(r0), "=r"(r1), "=r"(r2), "=r"(r3) : "r"(addr))

static __device__ __forceinline__ void mma_bf16(float* c, const uint32_t* a,
                                                uint32_t b0, uint32_t b1) {
    asm("mma.sync.aligned.m16n8k16.row.col.f32.bf16.bf16.f32 "
        "{%0,%1,%2,%3}, {%4,%5,%6,%7}, {%8,%9}, {%0,%1,%2,%3};"
        : "+f"(c[0]), "+f"(c[1]), "+f"(c[2]), "+f"(c[3])
        : "r"(a[0]), "r"(a[1]), "r"(a[2]), "r"(a[3]), "r"(b0), "r"(b1));
}

// bf16 hi/lo split of 2 packed floats (packed along k)
static __device__ __forceinline__ void bf16_split2(float a, float b, uint32_t& h, uint32_t& l) {
    __nv_bfloat162 hh = __float22bfloat162_rn(make_float2(a, b));
    float2 hf = __bfloat1622float2(hh);
    __nv_bfloat162 ll = __float22bfloat162_rn(make_float2(a - hf.x, b - hf.y));
    h = *reinterpret_cast<uint32_t*>(&hh);
    l = *reinterpret_cast<uint32_t*>(&ll);
}

__global__ void __launch_bounds__(THREADS_, 2)
afm_kernel(const float* __restrict__ gnn,
           const float* __restrict__ x,
           const float* __restrict__ W,
           const float* __restrict__ bias,
           float* __restrict__ out)
{
    extern __shared__ unsigned char smem_raw[];
    Smem* s = reinterpret_cast<Smem*>(smem_raw);

    const int b    = blockIdx.x;
    const int tid  = threadIdx.x;
    const int lane = tid & 31;
    const int wid  = tid >> 5;         // 0..7
    const int mi   = wid & 1;          // m-subtile (16 rows)
    const int ni   = wid >> 1;         // n-subtile (32 cols), 0..3
    const int rq   = lane >> 2;        // 0..7  (fragment row)
    const int kq   = 2 * (lane & 3);   // 0,2,4,6 (fragment col pair)

    // ---- pair table + zero scores ----
    for (int p = tid; p < P_; p += THREADS_) {
        int i = 0, base = 0;
        while (base + (F_ - 1 - i) <= p) { base += F_ - 1 - i; ++i; }
        int j = i + 1 + (p - base);
        s->pairs[p] = (unsigned short)((i << 8) | j);
        s->scores[p] = 0.f;
    }
    // ---- x[b] to smem ----
    const float4* xb = reinterpret_cast<const float4*>(x + (size_t)b * F_ * D_);
    for (int e = tid; e < F_ * D_ / 4; e += THREADS_) {
        int f = e >> 5, q = e & 31;
        *reinterpret_cast<float4*>(&s->xs[f][q * 4]) = xb[e];
    }
    if (tid < A_) {
        s->gnn_s[tid]  = gnn[(size_t)b * A_ + tid];
        s->bias_s[tid] = bias[tid];
    }
    // ---- W hi/lo bf16 tiles: W native [a][k], k-contiguous ----
    for (int e = tid; e < A_ * 16; e += THREADS_) {
        int a = e >> 4, kseg = e & 15, k0 = kseg * 8;
        const float4* wp = reinterpret_cast<const float4*>(W + a * D_ + k0);
        float4 w0 = wp[0], w1 = wp[1];
        uint4 hv, lv;
        bf16_split2(w0.x, w0.y, hv.x, lv.x);
        bf16_split2(w0.z, w0.w, hv.y, lv.y);
        bf16_split2(w1.x, w1.y, hv.z, lv.z);
        bf16_split2(w1.z, w1.w, hv.w, lv.w);
        *reinterpret_cast<uint4*>(&s->W_hi[a * SA + k0]) = hv;
        *reinterpret_cast<uint4*>(&s->W_lo[a * SA + k0]) = lv;
    }

    // ---- ldmatrix base addresses (byte, per-lane) ----
    // A x4 covers 16m x 16k
    const int arow = mi * 16 + (lane & 15);
    const int akb  = 8 * (lane >> 4);
    const uint32_t aAhi0 = smem_u32(&s->A_hi[arow * SA + akb]);
    const uint32_t aAlo0 = smem_u32(&s->A_lo[arow * SA + akb]);
    const uint32_t NSTEP = 16 * SA * 2;   // +16 B-rows, bytes
    // B x4 covers 16n x 16k
    const int brow = ni * 32 + (lane & 7) + 8 * (lane >> 4);
    const int bkb  = 8 * ((lane >> 3) & 1);
    const uint32_t bWhi0 = smem_u32(&s->W_hi[brow * SA + bkb]);
    const uint32_t bWlo0 = smem_u32(&s->W_lo[brow * SA + bkb]);

    // ==== main loop over 17 M-tiles of 32 pairs ====
    for (int t = 0; t < NT_TILES; ++t) {
        const int m0 = t * MT;
        __syncthreads();   // prior tile's A reads complete (and init done on t=0)

        // ---- fill inner tile hi/lo: A[mloc][k] = xs[i][k]*xs[j][k] ----
        for (int e = tid; e < MT * 16; e += THREADS_) {
            int mloc = e >> 4, kseg = e & 15, k0 = kseg * 8;
            int m = m0 + mloc;
            uint4 hv = make_uint4(0, 0, 0, 0), lv = make_uint4(0, 0, 0, 0);
            if (m < P_) {
                unsigned short pr = s->pairs[m];
                const float4* xi = reinterpret_cast<const float4*>(&s->xs[pr >> 8][k0]);
                const float4* xj = reinterpret_cast<const float4*>(&s->xs[pr & 255][k0]);
                float4 a0 = xi[0], a1 = xi[1], c0 = xj[0], c1 = xj[1];
                bf16_split2(a0.x * c0.x, a0.y * c0.y, hv.x, lv.x);
                bf16_split2(a0.z * c0.z, a0.w * c0.w, hv.y, lv.y);
                bf16_split2(a1.x * c1.x, a1.y * c1.y, hv.z, lv.z);
                bf16_split2(a1.z * c1.z, a1.w * c1.w, hv.w, lv.w);
            }
            *reinterpret_cast<uint4*>(&s->A_hi[mloc * SA + k0]) = hv;
            *reinterpret_cast<uint4*>(&s->A_lo[mloc * SA + k0]) = lv;
        }
        __syncthreads();

        // ---- warp-level GEMM: warp owns 16 rows x 32 cols ----
        float acc[4][4];   // [n-frag][quad]
#pragma unroll
        for (int nf = 0; nf < 4; ++nf)
#pragma unroll
            for (int q = 0; q < 4; ++q) acc[nf][q] = 0.f;

#pragma unroll
        for (int ks = 0; ks < 8; ++ks) {
            const uint32_t kb = ks * 32;   // 16 bf16 = 32 bytes
            uint32_t ah[4], al[4], bh[2][4], bl[2][4];
            LDSM_X4(ah[0], ah[1], ah[2], ah[3], aAhi0 + kb);
            LDSM_X4(al[0], al[1], al[2], al[3], aAlo0 + kb);
            LDSM_X4(bh[0][0], bh[0][1], bh[0][2], bh[0][3], bWhi0 + kb);
            LDSM_X4(bh[1][0], bh[1][1], bh[1][2], bh[1][3], bWhi0 + NSTEP + kb);
            LDSM_X4(bl[0][0], bl[0][1], bl[0][2], bl[0][3], bWlo0 + kb);
            LDSM_X4(bl[1][0], bl[1][1], bl[1][2], bl[1][3], bWlo0 + NSTEP + kb);
#pragma unroll
            for (int jn = 0; jn < 2; ++jn) {
                mma_bf16(acc[2 * jn],     ah, bh[jn][0], bh[jn][1]);
                mma_bf16(acc[2 * jn],     ah, bl[jn][0], bl[jn][1]);
                mma_bf16(acc[2 * jn],     al, bh[jn][0], bh[jn][1]);
                mma_bf16(acc[2 * jn + 1], ah, bh[jn][2], bh[jn][3]);
                mma_bf16(acc[2 * jn + 1], ah, bl[jn][2], bl[jn][3]);
                mma_bf16(acc[2 * jn + 1], al, bh[jn][2], bh[jn][3]);
            }
        }

        // ---- epilogue: bias + relu + gnn dot over this warp's 32 cols ----
        float sc0 = 0.f, sc1 = 0.f;
#pragma unroll
        for (int nf = 0; nf < 4; ++nf) {
            const int n0 = ni * 32 + nf * 8 + kq;
            float g0 = s->gnn_s[n0], g1 = s->gnn_s[n0 + 1];
            float b0 = s->bias_s[n0], b1 = s->bias_s[n0 + 1];
            sc0 = fmaf(g0, fmaxf(acc[nf][0] + b0, 0.f), sc0);
            sc0 = fmaf(g1, fmaxf(acc[nf][1] + b1, 0.f), sc0);
            sc1 = fmaf(g0, fmaxf(acc[nf][2] + b0, 0.f), sc1);
            sc1 = fmaf(g1, fmaxf(acc[nf][3] + b1, 0.f), sc1);
        }
        sc0 += __shfl_xor_sync(0xffffffffu, sc0, 1);
        sc0 += __shfl_xor_sync(0xffffffffu, sc0, 2);
        sc1 += __shfl_xor_sync(0xffffffffu, sc1, 1);
        sc1 += __shfl_xor_sync(0xffffffffu, sc1, 2);
        if ((lane & 3) == 0) {
            int ma = m0 + mi * 16 + rq;   // 4 n-warps add per row
            if (ma < P_)     atomicAdd(&s->scores[ma],     sc0);
            if (ma + 8 < P_) atomicAdd(&s->scores[ma + 8], sc1);
        }
    }
    __syncthreads();

    // ==== softmax over scores[528] ====
    float lmax = -1e30f;
    for (int p = tid; p < P_; p += THREADS_) lmax = fmaxf(lmax, s->scores[p]);
#pragma unroll
    for (int o = 16; o; o >>= 1) lmax = fmaxf(lmax, __shfl_xor_sync(0xffffffffu, lmax, o));
    if (lane == 0) s->red[wid] = lmax;
    __syncthreads();
    if (tid < 32) {
        float v = (tid < 8) ? s->red[tid] : -1e30f;
#pragma unroll
        for (int o = 4; o; o >>= 1) v = fmaxf(v, __shfl_xor_sync(0xffffffffu, v, o));
        if (tid == 0) s->red[8] = v;
    }
    __syncthreads();
    const float mx = s->red[8];

    float lsum = 0.f;
    for (int p = tid; p < P_; p += THREADS_) {
        float e = __expf(s->scores[p] - mx);
        s->scores[p] = e;
        lsum += e;
    }
#pragma unroll
    for (int o = 16; o; o >>= 1) lsum += __shfl_xor_sync(0xffffffffu, lsum, o);
    if (lane == 0) s->red[wid] = lsum;
    __syncthreads();
    if (tid < 32) {
        float v = (tid < 8) ? s->red[tid] : 0.f;
#pragma unroll
        for (int o = 4; o; o >>= 1) v += __shfl_xor_sync(0xffffffffu, v, o);
        if (tid == 0) s->red[9] = v;
    }
    __syncthreads();
    const float scale = 100.f / s->red[9];

    // ==== attn_output[d] = scale * sum_p exp_p * xs[i][d]*xs[j][d] ====
    const int d    = tid & 127;
    const int half = tid >> 7;
    float accd = 0.f;
    const int pstart = half * (P_ / 2);
    for (int p = pstart; p < pstart + P_ / 2; ++p) {
        unsigned short pr = s->pairs[p];
        accd = fmaf(s->scores[p], s->xs[pr >> 8][d] * s->xs[pr & 255][d], accd);
    }
    s->part[half * 128 + d] = accd;
    __syncthreads();

    float* outb = out + (size_t)b * (A_ + D_);
    if (tid < 128) {
        outb[tid]       = s->gnn_s[tid];
        outb[128 + tid] = (s->part[tid] + s->part[128 + tid]) * scale;
    }
}

extern "C" void kernel_launch(void* const* d_in, const int* in_sizes, int n_in,
                              void* d_out, int out_size)
{
    const float* gnn  = (const float*)d_in[0];   // [B, 128]
    const float* x    = (const float*)d_in[1];   // [B, 33, 128]
    const float* W    = (const float*)d_in[2];   // [128, 128]
    const float* bias = (const float*)d_in[3];   // [128]
    float* out        = (float*)d_out;           // [B, 256]

    const int B = in_sizes[0] / A_;
    const int smem_bytes = (int)sizeof(Smem);

    cudaFuncSetAttribute(afm_kernel, cudaFuncAttributeMaxDynamicSharedMemorySize, smem_bytes);
    afm_kernel<<<B, THREADS_, smem_bytes>>>(gnn, x, W, bias, out);
}